// round 16
// baseline (speedup 1.0000x reference)
#include <cuda_runtime.h>
#include <cuda_bf16.h>
#include <math.h>
#include <stdint.h>

// ---------------- problem constants ----------------
#define D_MODEL 1024
#define D_STATE 16
#define D_CONV 4
#define D_INNER 2048
#define DT_RANK 64
#define B_SZ 2
#define SEQ 1024
#define NROWS (B_SZ * SEQ)              // 2048
#define XDBL_N 96
#define XDBL_P 128                       // padded stride for xdbl
#define NCH 8
#define CHUNK 128                        // SEQ / NCH

// ---------------- scratch (device globals; no allocation allowed) ----------
__device__ float g_xz[NROWS * 2 * D_INNER];
__device__ uint32_t g_xcp[NROWS * D_INNER];       // packed bf16 (hi<<16)|lo of xc
__device__ float g_delta[NROWS * D_INNER];
__device__ __align__(16) float g_xdbl[NROWS * XDBL_P];
__device__ float g_part[16 * NROWS * XDBL_P];

__device__ __nv_bfloat16 g_xh[NROWS * D_MODEL];
__device__ __nv_bfloat16 g_xl[NROWS * D_MODEL];
__device__ __nv_bfloat16 g_xch[NROWS * D_INNER];
__device__ __nv_bfloat16 g_xcl[NROWS * D_INNER];
__device__ __nv_bfloat16 g_winh[2 * D_INNER * D_MODEL];
__device__ __nv_bfloat16 g_winl[2 * D_INNER * D_MODEL];
__device__ __nv_bfloat16 g_wxh[XDBL_P * D_INNER];
__device__ __nv_bfloat16 g_wxl[XDBL_P * D_INNER];
__device__ __nv_bfloat16 g_yh[NROWS * D_INNER];
__device__ __nv_bfloat16 g_yl[NROWS * D_INNER];
__device__ __nv_bfloat16 g_woh[D_MODEL * D_INNER];
__device__ __nv_bfloat16 g_wol[D_MODEL * D_INNER];
__device__ __nv_bfloat16 g_drh[NROWS * DT_RANK];
__device__ __nv_bfloat16 g_drl[NROWS * DT_RANK];
__device__ __nv_bfloat16 g_wdth[D_INNER * DT_RANK];
__device__ __nv_bfloat16 g_wdtl[D_INNER * DT_RANK];

// ======================= HMMA bf16 split GEMM ===============================
#define BUF_BYTES  32768
#define OAL 8192
#define OBH 16384
#define OBL 24576

__device__ __forceinline__ uint32_t smem_u32(const void* p) {
    uint32_t a;
    asm("{ .reg .u64 t; cvta.to.shared.u64 t, %1; cvt.u32.u64 %0, t; }"
        : "=r"(a) : "l"(p));
    return a;
}

#define CP_ASYNC16(sa, gp) \
    asm volatile("cp.async.cg.shared.global [%0], [%1], 16;" :: "r"(sa), "l"(gp))
#define CP_COMMIT() asm volatile("cp.async.commit_group;")
#define CP_WAIT1()  asm volatile("cp.async.wait_group 1;")

#define LDX4(r0, r1, r2, r3, a)                                                  \
    asm volatile("ldmatrix.sync.aligned.m8n8.x4.shared.b16 {%0,%1,%2,%3}, [%4];" \
                 : "=r"(r0), "=r"(r1), "=r"(r2), "=r"(r3) : "r"(a))

__device__ __forceinline__ void mma_bf16(float* c, const uint32_t* a, const uint32_t* b) {
    asm volatile(
        "mma.sync.aligned.m16n8k16.row.col.f32.bf16.bf16.f32 "
        "{%0,%1,%2,%3}, {%4,%5,%6,%7}, {%8,%9}, {%0,%1,%2,%3};"
        : "+f"(c[0]), "+f"(c[1]), "+f"(c[2]), "+f"(c[3])
        : "r"(a[0]), "r"(a[1]), "r"(a[2]), "r"(a[3]), "r"(b[0]), "r"(b[1]));
}

// EPI==0: plain float2 stores. EPI==1: v += bias[col]; softplus; float2 stores.
template <int EPI>
__global__ __launch_bounds__(256, 2)
void hmma_gemm(const __nv_bfloat16* __restrict__ Ah, const __nv_bfloat16* __restrict__ Al,
               const __nv_bfloat16* __restrict__ Bh, const __nv_bfloat16* __restrict__ Bl,
               float* __restrict__ C, const float* __restrict__ bias,
               int K, int N, int Kpart)
{
    extern __shared__ __align__(128) char s[];
    const uint32_t sb = smem_u32(s);

    const int tid  = threadIdx.x;
    const int wid  = tid >> 5;
    const int lane = tid & 31;
    const int wm   = wid >> 2;
    const int wn   = wid & 3;

    const int brow  = blockIdx.y * 128;
    const int bcol  = blockIdx.x * 128;
    const int kbase = blockIdx.z * Kpart;
    C += (size_t)blockIdx.z * (size_t)(gridDim.y * 128) * N;

    float acc[4][4][4];
#pragma unroll
    for (int i = 0; i < 4; i++)
#pragma unroll
        for (int j = 0; j < 4; j++)
#pragma unroll
            for (int q = 0; q < 4; q++) acc[i][j][q] = 0.f;

    const int l_r0 = tid >> 2;
    const int l_k  = tid & 3;

#define LOAD_CHUNK(cidx, bufi)                                                    \
    {                                                                             \
        const int k0 = kbase + ((cidx) << 5);                                     \
        const uint32_t bbase = sb + (bufi) * BUF_BYTES;                           \
        _Pragma("unroll")                                                         \
        for (int i0 = 0; i0 < 2; i0++) {                                          \
            const int r = l_r0 + i0 * 64;                                         \
            const uint32_t so = (uint32_t)(r * 64 + ((l_k ^ ((r >> 1) & 3)) << 4)); \
            const size_t ga = (size_t)(brow + r) * K + k0 + l_k * 8;              \
            const size_t gb = (size_t)(bcol + r) * K + k0 + l_k * 8;              \
            CP_ASYNC16(bbase + so,        Ah + ga);                               \
            CP_ASYNC16(bbase + OAL + so,  Al + ga);                               \
            CP_ASYNC16(bbase + OBH + so,  Bh + gb);                               \
            CP_ASYNC16(bbase + OBL + so,  Bl + gb);                               \
        }                                                                         \
    }

    const int g  = lane >> 3;
    const int li = lane & 7;
    const int swz = (li >> 1) & 3;
    const int rowA = wm * 64 + li + (g & 1) * 8;
    const int khA  = g >> 1;
    const int rowB = wn * 32 + li + (g >> 1) * 8;
    const int khB  = g & 1;
    uint32_t aoffs[2], boffs[2];
#pragma unroll
    for (int sN = 0; sN < 2; sN++) {
        aoffs[sN] = (uint32_t)(rowA * 64 + (((2 * sN + khA) ^ swz) << 4));
        boffs[sN] = (uint32_t)(OBH + rowB * 64 + (((2 * sN + khB) ^ swz) << 4));
    }

#define COMPUTE_STEP(sidx, bofs)                                                  \
    {                                                                             \
        const uint32_t aA = sb + (bofs) + aoffs[sidx];                            \
        const uint32_t bB = sb + (bofs) + boffs[sidx];                            \
        uint32_t bh[4][2], bl[4][2];                                              \
        LDX4(bh[0][0], bh[0][1], bh[1][0], bh[1][1], bB);                         \
        LDX4(bh[2][0], bh[2][1], bh[3][0], bh[3][1], bB + 1024);                  \
        LDX4(bl[0][0], bl[0][1], bl[1][0], bl[1][1], bB + 8192);                  \
        LDX4(bl[2][0], bl[2][1], bl[3][0], bl[3][1], bB + 8192 + 1024);           \
        _Pragma("unroll")                                                         \
        for (int half = 0; half < 2; half++) {                                    \
            uint32_t ah[2][4], al[2][4];                                          \
            const uint32_t ab = aA + half * 2048;                                 \
            LDX4(ah[0][0], ah[0][1], ah[0][2], ah[0][3], ab);                     \
            LDX4(ah[1][0], ah[1][1], ah[1][2], ah[1][3], ab + 1024);              \
            LDX4(al[0][0], al[0][1], al[0][2], al[0][3], ab + OAL);               \
            LDX4(al[1][0], al[1][1], al[1][2], al[1][3], ab + OAL + 1024);        \
            _Pragma("unroll")                                                     \
            for (int m2 = 0; m2 < 2; m2++)                                        \
                _Pragma("unroll")                                                 \
                for (int nt = 0; nt < 4; nt++)                                    \
                    mma_bf16(acc[half * 2 + m2][nt], ah[m2], bh[nt]);             \
            _Pragma("unroll")                                                     \
            for (int m2 = 0; m2 < 2; m2++)                                        \
                _Pragma("unroll")                                                 \
                for (int nt = 0; nt < 4; nt++)                                    \
                    mma_bf16(acc[half * 2 + m2][nt], ah[m2], bl[nt]);             \
            _Pragma("unroll")                                                     \
            for (int m2 = 0; m2 < 2; m2++)                                        \
                _Pragma("unroll")                                                 \
                for (int nt = 0; nt < 4; nt++)                                    \
                    mma_bf16(acc[half * 2 + m2][nt], al[m2], bh[nt]);             \
        }                                                                         \
    }

    const int nchunks = Kpart >> 5;
    LOAD_CHUNK(0, 0); CP_COMMIT();
    if (nchunks > 1) { LOAD_CHUNK(1, 1); }
    CP_COMMIT();

    int buf = 0;
    for (int c = 0; c < nchunks; c++) {
        CP_WAIT1();
        __syncthreads();
        const int cn = c + 2;
        int nbuf = buf + 2; if (nbuf >= 3) nbuf -= 3;
        if (cn < nchunks) LOAD_CHUNK(cn, nbuf);
        CP_COMMIT();
        const uint32_t bofs = (uint32_t)(buf * BUF_BYTES);
        COMPUTE_STEP(0, bofs);
        COMPUTE_STEP(1, bofs);
        if (++buf == 3) buf = 0;
    }

    const int frow = lane >> 2;
    const int fcol = (lane & 3) << 1;
#pragma unroll
    for (int mt = 0; mt < 4; mt++) {
        const int row = brow + wm * 64 + mt * 16 + frow;
#pragma unroll
        for (int nt = 0; nt < 4; nt++) {
            const int col = bcol + wn * 32 + nt * 8 + fcol;
            float v0 = acc[mt][nt][0], v1 = acc[mt][nt][1];
            float v2 = acc[mt][nt][2], v3 = acc[mt][nt][3];
            if (EPI == 1) {
                const float b0 = bias[col], b1 = bias[col + 1];
                v0 += b0; v1 += b1; v2 += b0; v3 += b1;
                v0 = (v0 > 20.f) ? v0 : log1pf(__expf(v0));
                v1 = (v1 > 20.f) ? v1 : log1pf(__expf(v1));
                v2 = (v2 > 20.f) ? v2 : log1pf(__expf(v2));
                v3 = (v3 > 20.f) ? v3 : log1pf(__expf(v3));
            }
            *(float2*)&C[(size_t)row * N + col]       = make_float2(v0, v1);
            *(float2*)&C[(size_t)(row + 8) * N + col] = make_float2(v2, v3);
        }
    }
#undef LOAD_CHUNK
#undef COMPUTE_STEP
}

// ---------- split-K=2 reduce (GEMM4) ----------------------------------------
__global__ __launch_bounds__(256)
void reduce2_kernel(const float* __restrict__ p, float* __restrict__ out, int n4)
{
    int i = blockIdx.x * 256 + threadIdx.x;
    if (i >= n4) return;
    const float4* p0 = (const float4*)p;
    const float4* p1 = p0 + n4;
    float4 a = p0[i], b = p1[i];
    ((float4*)out)[i] = make_float4(a.x + b.x, a.y + b.y, a.z + b.z, a.w + b.w);
}

// ---------- split-K=16 reduce for xdbl (+ fold delta_r bf16 split) -----------
__global__ __launch_bounds__(256)
void reduce16_xdbl_kernel()
{
    const int n4 = NROWS * XDBL_P / 4;      // 65536
    int i = blockIdx.x * 256 + threadIdx.x;
    if (i >= n4) return;
    float4 s = make_float4(0.f, 0.f, 0.f, 0.f);
    const float4* p = (const float4*)g_part;
#pragma unroll
    for (int k = 0; k < 16; k++) {
        float4 v = p[(size_t)k * n4 + i];
        s.x += v.x; s.y += v.y; s.z += v.z; s.w += v.w;
    }
    ((float4*)g_xdbl)[i] = s;
    const int row = i >> 5;
    const int c4  = (i & 31) << 2;
    if (c4 < DT_RANK) {
        const size_t o = (size_t)row * DT_RANK + c4;
        float vv[4] = {s.x, s.y, s.z, s.w};
#pragma unroll
        for (int q = 0; q < 4; q++) {
            __nv_bfloat16 h = __float2bfloat16(vv[q]);
            g_drh[o + q] = h;
            g_drl[o + q] = __float2bfloat16(vv[q] - __bfloat162float(h));
        }
    }
}

// ---- fused prep: x split (vec4) + transpose+split of weights + W_x pad -----
__device__ __forceinline__ void tsplit_tile(
    const float* __restrict__ W, __nv_bfloat16* __restrict__ Th,
    __nv_bfloat16* __restrict__ Tl, int K, int N, int bx, int by, int tid)
{
    __shared__ float t[32][33];
    const int tx = tid & 31;
    const int ty = tid >> 5;
    const int n0 = bx * 32;
    const int k0 = by * 32;
#pragma unroll
    for (int s2 = 0; s2 < 32; s2 += 8)
        t[ty + s2][tx] = W[(size_t)(k0 + ty + s2) * N + n0 + tx];
    __syncthreads();
#pragma unroll
    for (int s2 = 0; s2 < 32; s2 += 8) {
        float v = t[tx][ty + s2];
        __nv_bfloat16 h = __float2bfloat16(v);
        const size_t o = (size_t)(n0 + ty + s2) * K + k0 + tx;
        Th[o] = h;
        Tl[o] = __float2bfloat16(v - __bfloat162float(h));
    }
}

// [0,2048): x split vec4 | [2048,6144): W_in | [6144,8192): W_out
// [8192,8320): W_dt | [8320,8512): W_x tiles | [8512,8768): W_x pad zero
__global__ __launch_bounds__(256)
void prep_all_kernel(const float* __restrict__ x, const float* __restrict__ W_in,
                     const float* __restrict__ W_out, const float* __restrict__ W_dt,
                     const float* __restrict__ W_x)
{
    const int id = blockIdx.x;
    const int tid = threadIdx.x;
    if (id < 2048) {
        const int i4 = (id * 256 + tid) * 4;
        float4 v = *(const float4*)(x + i4);
        float vv[4] = {v.x, v.y, v.z, v.w};
#pragma unroll
        for (int q = 0; q < 4; q++) {
            __nv_bfloat16 h = __float2bfloat16(vv[q]);
            g_xh[i4 + q] = h;
            g_xl[i4 + q] = __float2bfloat16(vv[q] - __bfloat162float(h));
        }
    } else if (id < 6144) {
        const int j = id - 2048;
        tsplit_tile(W_in, g_winh, g_winl, D_MODEL, 2 * D_INNER, j & 127, j >> 7, tid);
    } else if (id < 8192) {
        const int j = id - 6144;
        tsplit_tile(W_out, g_woh, g_wol, D_INNER, D_MODEL, j & 31, j >> 5, tid);
    } else if (id < 8320) {
        const int j = id - 8192;
        tsplit_tile(W_dt, g_wdth, g_wdtl, DT_RANK, D_INNER, j & 63, j >> 6, tid);
    } else if (id < 8512) {
        const int j = id - 8320;
        tsplit_tile(W_x, g_wxh, g_wxl, D_INNER, XDBL_N, j % 3, j / 3, tid);
    } else {
        const int j = (id - 8512) * 256 + tid;
        const int base = XDBL_N * D_INNER;
        g_wxh[base + j] = __float2bfloat16(0.f);
        g_wxl[base + j] = __float2bfloat16(0.f);
    }
}

// ---------- depthwise causal conv (k=4) + SiLU, 8 steps/thread --------------
// writes xch/xcl (for HMMA) and packed xcp (for scan). No fp32 xc/zs arrays.
__global__ __launch_bounds__(256)
void conv_silu8_kernel(const float* __restrict__ conv_w, const float* __restrict__ conv_b)
{
    int i = blockIdx.x * 256 + threadIdx.x;
    if (i >= (NROWS / 8) * D_INNER) return;
    const int d    = i & (D_INNER - 1);
    const int grp  = i >> 11;
    const int row0 = grp << 3;
    const int l0   = row0 & (SEQ - 1);

    const float w0 = conv_w[d * 4 + 0];
    const float w1 = conv_w[d * 4 + 1];
    const float w2 = conv_w[d * 4 + 2];
    const float w3 = conv_w[d * 4 + 3];
    const float bb = conv_b[d];

    const float* xe = g_xz + (size_t)row0 * (2 * D_INNER) + d;
    float xv[11];
    if (l0 > 0) {
        xv[0] = xe[-3 * 2 * D_INNER];
        xv[1] = xe[-2 * 2 * D_INNER];
        xv[2] = xe[-1 * 2 * D_INNER];
    } else {
        xv[0] = xv[1] = xv[2] = 0.f;
    }
#pragma unroll
    for (int k = 0; k < 8; k++)
        xv[3 + k] = xe[(size_t)k * 2 * D_INNER];

#pragma unroll
    for (int k = 0; k < 8; k++) {
        float a = bb;
        a = fmaf(w0, xv[k],     a);
        a = fmaf(w1, xv[k + 1], a);
        a = fmaf(w2, xv[k + 2], a);
        a = fmaf(w3, xv[k + 3], a);
        const float xc = a / (1.f + __expf(-a));
        const size_t o = (size_t)(row0 + k) * D_INNER + d;
        __nv_bfloat16 h = __float2bfloat16(xc);
        __nv_bfloat16 l = __float2bfloat16(xc - __bfloat162float(h));
        g_xch[o] = h;
        g_xcl[o] = l;
        g_xcp[o] = ((uint32_t)__bfloat16_as_ushort(h) << 16) |
                   (uint32_t)__bfloat16_as_ushort(l);
    }
}

// ================== fused chunked selective scan (r12 layout) ================
// Block = 256 threads = 8 warps (warp = chunk); block covers 2 channels.
// xc from packed bf16 pair; silu(z) computed from g_xz in phase 3.
__global__ __launch_bounds__(256)
void scan_fused(const float* __restrict__ A_log, const float* __restrict__ Dp)
{
    __shared__ float sm_hend[NCH][32];
    __shared__ float sm_P[NCH][32];
    __shared__ float sm_hin[NCH][32];

    const int tid    = threadIdx.x;
    const int w      = tid >> 5;
    const int lane   = tid & 31;
    const int half   = lane >> 4;
    const int lane16 = lane & 15;
    const int chan   = (blockIdx.x << 1) | half;
    const int b      = blockIdx.y;

    const float Aval = -__expf(A_log[chan * D_STATE + lane16]);
    const float Dd   = Dp[chan];

    const size_t rbase = (size_t)b * SEQ + (size_t)w * CHUNK;
    const float*    dl = g_delta + rbase * D_INNER + chan;
    const uint32_t* xp = g_xcp   + rbase * D_INNER + chan;
    const float*    zr = g_xz    + rbase * (2 * D_INNER) + D_INNER + chan;
    const float*    bp = g_xdbl  + rbase * XDBL_P + DT_RANK + lane16;
    const float*    cp = bp + D_STATE;

#define UNPACK_XC(p)                                                              \
    (__bfloat162float(__ushort_as_bfloat16((unsigned short)((p) >> 16))) +        \
     __bfloat162float(__ushort_as_bfloat16((unsigned short)((p) & 0xFFFFu))))

    // ---- phase 1: local scan from h=0, track decay product
    {
        float pdv[4], pBn[4];
        uint32_t pxc[4];
#pragma unroll
        for (int u = 0; u < 4; u++) {
            pdv[u] = dl[u * D_INNER];
            pxc[u] = xp[u * D_INNER];
            pBn[u] = bp[u * XDBL_P];
        }
        const float* dll = dl;
        const uint32_t* xpp = xp;
        const float* bpp = bp;
        float h = 0.f, P = 1.f;
        for (int l = 0; l < CHUNK; l += 4) {
            float dv[4], Bn[4];
            uint32_t xc[4];
#pragma unroll
            for (int u = 0; u < 4; u++) { dv[u] = pdv[u]; xc[u] = pxc[u]; Bn[u] = pBn[u]; }
            dll += 4 * D_INNER; xpp += 4 * D_INNER; bpp += 4 * XDBL_P;
            if (l + 4 < CHUNK) {
#pragma unroll
                for (int u = 0; u < 4; u++) {
                    pdv[u] = dll[u * D_INNER];
                    pxc[u] = xpp[u * D_INNER];
                    pBn[u] = bpp[u * XDBL_P];
                }
            }
#pragma unroll
            for (int u = 0; u < 4; u++) {
                const float dA = __expf(dv[u] * Aval);
                h = fmaf(dA, h, dv[u] * UNPACK_XC(xc[u]) * Bn[u]);
                P *= dA;
            }
        }
        sm_hend[w][lane] = h;
        sm_P[w][lane]    = P;
    }
    __syncthreads();

    // ---- carry combine
    if (tid < 32) {
        float H = 0.f;
#pragma unroll
        for (int c = 0; c < NCH; c++) {
            sm_hin[c][tid] = H;
            H = fmaf(sm_P[c][tid], H, sm_hend[c][tid]);
        }
    }
    __syncthreads();

    // ---- phase 3: rerun with carry-in, emit y
    {
        __nv_bfloat16* yh = g_yh + rbase * D_INNER + chan;
        __nv_bfloat16* yl = g_yl + rbase * D_INNER + chan;

        float pdv[4], pBn[4], pCn[4], pz[4];
        uint32_t pxc[4];
#pragma unroll
        for (int u = 0; u < 4; u++) {
            pdv[u] = dl[u * D_INNER];
            pxc[u] = xp[u * D_INNER];
            pz[u]  = zr[u * 2 * D_INNER];
            pBn[u] = bp[u * XDBL_P];
            pCn[u] = cp[u * XDBL_P];
        }
        float h = sm_hin[w][lane];

        for (int l = 0; l < CHUNK; l += 4) {
            float dv[4], Bn[4], Cn[4], zraw[4];
            uint32_t xc[4];
#pragma unroll
            for (int u = 0; u < 4; u++) {
                dv[u] = pdv[u]; xc[u] = pxc[u]; zraw[u] = pz[u];
                Bn[u] = pBn[u]; Cn[u] = pCn[u];
            }
            dl += 4 * D_INNER; xp += 4 * D_INNER; zr += 4 * 2 * D_INNER;
            bp += 4 * XDBL_P;  cp += 4 * XDBL_P;
            if (l + 4 < CHUNK) {
#pragma unroll
                for (int u = 0; u < 4; u++) {
                    pdv[u] = dl[u * D_INNER];
                    pxc[u] = xp[u * D_INNER];
                    pz[u]  = zr[u * 2 * D_INNER];
                    pBn[u] = bp[u * XDBL_P];
                    pCn[u] = cp[u * XDBL_P];
                }
            }

            float contrib[4], xvv[4];
#pragma unroll
            for (int u = 0; u < 4; u++) {
                const float dA = __expf(dv[u] * Aval);
                xvv[u] = UNPACK_XC(xc[u]);
                h = fmaf(dA, h, dv[u] * xvv[u] * Bn[u]);
                contrib[u] = h * Cn[u];
            }
#pragma unroll
            for (int u = 0; u < 4; u++) {
                contrib[u] += __shfl_down_sync(0xffffffffu, contrib[u], 8, 16);
                contrib[u] += __shfl_down_sync(0xffffffffu, contrib[u], 4, 16);
                contrib[u] += __shfl_down_sync(0xffffffffu, contrib[u], 2, 16);
                contrib[u] += __shfl_down_sync(0xffffffffu, contrib[u], 1, 16);
            }
            if (lane16 == 0) {
#pragma unroll
                for (int u = 0; u < 4; u++) {
                    const float zs = zraw[u] / (1.f + __expf(-zraw[u]));
                    float v = fmaf(xvv[u], Dd, contrib[u]) * zs;
                    __nv_bfloat16 hh = __float2bfloat16(v);
                    yh[(size_t)(l + u) * D_INNER] = hh;
                    yl[(size_t)(l + u) * D_INNER] =
                        __float2bfloat16(v - __bfloat162float(hh));
                }
            }
        }
    }
#undef UNPACK_XC
}

// ---------------- launch ----------------------------------------------------
extern "C" void kernel_launch(void* const* d_in, const int* in_sizes, int n_in,
                              void* d_out, int out_size)
{
    const float* x      = (const float*)d_in[0];
    const float* W_in   = (const float*)d_in[1];
    const float* conv_w = (const float*)d_in[2];
    const float* conv_b = (const float*)d_in[3];
    const float* W_x    = (const float*)d_in[4];
    const float* W_dt   = (const float*)d_in[5];
    const float* b_dt   = (const float*)d_in[6];
    const float* A_log  = (const float*)d_in[7];
    const float* Dp     = (const float*)d_in[8];
    const float* W_out  = (const float*)d_in[9];
    float* out = (float*)d_out;

    float *xz, *part, *delta;
    __nv_bfloat16 *xh, *xl, *xch, *xcl, *winh, *winl, *wxh, *wxl;
    __nv_bfloat16 *yh, *yl, *woh, *wol, *drh, *drl, *wdth, *wdtl;
    cudaGetSymbolAddress((void**)&xz,    g_xz);
    cudaGetSymbolAddress((void**)&part,  g_part);
    cudaGetSymbolAddress((void**)&delta, g_delta);
    cudaGetSymbolAddress((void**)&xh,   g_xh);
    cudaGetSymbolAddress((void**)&xl,   g_xl);
    cudaGetSymbolAddress((void**)&xch,  g_xch);
    cudaGetSymbolAddress((void**)&xcl,  g_xcl);
    cudaGetSymbolAddress((void**)&winh, g_winh);
    cudaGetSymbolAddress((void**)&winl, g_winl);
    cudaGetSymbolAddress((void**)&wxh,  g_wxh);
    cudaGetSymbolAddress((void**)&wxl,  g_wxl);
    cudaGetSymbolAddress((void**)&yh,   g_yh);
    cudaGetSymbolAddress((void**)&yl,   g_yl);
    cudaGetSymbolAddress((void**)&woh,  g_woh);
    cudaGetSymbolAddress((void**)&wol,  g_wol);
    cudaGetSymbolAddress((void**)&drh,  g_drh);
    cudaGetSymbolAddress((void**)&drl,  g_drl);
    cudaGetSymbolAddress((void**)&wdth, g_wdth);
    cudaGetSymbolAddress((void**)&wdtl, g_wdtl);

    const int HSMEM = 3 * BUF_BYTES;  // 98304
    cudaFuncSetAttribute(hmma_gemm<0>, cudaFuncAttributeMaxDynamicSharedMemorySize, HSMEM);
    cudaFuncSetAttribute(hmma_gemm<1>, cudaFuncAttributeMaxDynamicSharedMemorySize, HSMEM);

    // 0) fused prep
    prep_all_kernel<<<8768, 256>>>(x, W_in, W_out, W_dt, W_x);

    // 1) xz = x @ W_in
    hmma_gemm<0><<<dim3(2 * D_INNER / 128, NROWS / 128, 1), 256, HSMEM>>>(
        xh, xl, winh, winl, xz, nullptr, D_MODEL, 2 * D_INNER, D_MODEL);

    // 2) xc = silu(conv(x_e)+b) -> xch/xcl + packed xcp
    conv_silu8_kernel<<<(NROWS / 8 * D_INNER + 255) / 256, 256>>>(conv_w, conv_b);

    // 3) xdbl = xc @ W_x  (HMMA, N=128 padded, split-K=16)
    hmma_gemm<0><<<dim3(1, NROWS / 128, 16), 256, HSMEM>>>(
        xch, xcl, wxh, wxl, part, nullptr, D_INNER, XDBL_P, D_INNER / 16);
    reduce16_xdbl_kernel<<<(NROWS * XDBL_P / 4 + 255) / 256, 256>>>();

    // 4) delta = softplus(delta_r @ W_dt + b_dt)  (HMMA, K=64)
    hmma_gemm<1><<<dim3(D_INNER / 128, NROWS / 128, 1), 256, HSMEM>>>(
        drh, drl, wdth, wdtl, delta, b_dt, DT_RANK, D_INNER, DT_RANK);

    // 5) fused chunked selective scan -> yh/yl
    scan_fused<<<dim3(D_INNER / 2, B_SZ), 256>>>(A_log, Dp);

    // 6) out = y @ W_out  (split-K=2)
    hmma_gemm<0><<<dim3(D_MODEL / 128, NROWS / 128, 2), 256, HSMEM>>>(
        yh, yl, woh, wol, part, nullptr, D_INNER, D_MODEL, D_INNER / 2);
    reduce2_kernel<<<(NROWS * D_MODEL / 4 + 255) / 256, 256>>>(
        part, out, NROWS * D_MODEL / 4);
}

// round 17
// speedup vs baseline: 1.0581x; 1.0581x over previous
#include <cuda_runtime.h>
#include <cuda_bf16.h>
#include <math.h>
#include <stdint.h>

// ---------------- problem constants ----------------
#define D_MODEL 1024
#define D_STATE 16
#define D_CONV 4
#define D_INNER 2048
#define DT_RANK 64
#define B_SZ 2
#define SEQ 1024
#define NROWS (B_SZ * SEQ)              // 2048
#define XDBL_N 96
#define XDBL_P 128                       // padded stride for xdbl
#define NCH 8
#define CHUNK 128                        // SEQ / NCH

// ---------------- scratch (device globals; no allocation allowed) ----------
__device__ float g_xz[NROWS * 2 * D_INNER];
__device__ float g_xc[NROWS * D_INNER];
__device__ float g_zs[NROWS * D_INNER];
__device__ float g_delta[NROWS * D_INNER];
__device__ __align__(16) float g_xdbl[NROWS * XDBL_P];
__device__ float g_part[16 * NROWS * XDBL_P];

__device__ __nv_bfloat16 g_xh[NROWS * D_MODEL];
__device__ __nv_bfloat16 g_xl[NROWS * D_MODEL];
__device__ __nv_bfloat16 g_xch[NROWS * D_INNER];
__device__ __nv_bfloat16 g_xcl[NROWS * D_INNER];
__device__ __nv_bfloat16 g_winh[2 * D_INNER * D_MODEL];
__device__ __nv_bfloat16 g_winl[2 * D_INNER * D_MODEL];
__device__ __nv_bfloat16 g_wxh[XDBL_P * D_INNER];
__device__ __nv_bfloat16 g_wxl[XDBL_P * D_INNER];
__device__ __nv_bfloat16 g_yh[NROWS * D_INNER];
__device__ __nv_bfloat16 g_yl[NROWS * D_INNER];
__device__ __nv_bfloat16 g_woh[D_MODEL * D_INNER];
__device__ __nv_bfloat16 g_wol[D_MODEL * D_INNER];
__device__ __nv_bfloat16 g_drh[NROWS * DT_RANK];
__device__ __nv_bfloat16 g_drl[NROWS * DT_RANK];
__device__ __nv_bfloat16 g_wdth[D_INNER * DT_RANK];
__device__ __nv_bfloat16 g_wdtl[D_INNER * DT_RANK];

// ======================= HMMA bf16 split GEMM ===============================
#define BUF_BYTES  32768
#define OAL 8192
#define OBH 16384
#define OBL 24576

__device__ __forceinline__ uint32_t smem_u32(const void* p) {
    uint32_t a;
    asm("{ .reg .u64 t; cvta.to.shared.u64 t, %1; cvt.u32.u64 %0, t; }"
        : "=r"(a) : "l"(p));
    return a;
}

#define CP_ASYNC16(sa, gp) \
    asm volatile("cp.async.cg.shared.global [%0], [%1], 16;" :: "r"(sa), "l"(gp))
#define CP_COMMIT() asm volatile("cp.async.commit_group;")
#define CP_WAIT1()  asm volatile("cp.async.wait_group 1;")

#define LDX4(r0, r1, r2, r3, a)                                                  \
    asm volatile("ldmatrix.sync.aligned.m8n8.x4.shared.b16 {%0,%1,%2,%3}, [%4];" \
                 : "=r"(r0), "=r"(r1), "=r"(r2), "=r"(r3) : "r"(a))

__device__ __forceinline__ void mma_bf16(float* c, const uint32_t* a, const uint32_t* b) {
    asm volatile(
        "mma.sync.aligned.m16n8k16.row.col.f32.bf16.bf16.f32 "
        "{%0,%1,%2,%3}, {%4,%5,%6,%7}, {%8,%9}, {%0,%1,%2,%3};"
        : "+f"(c[0]), "+f"(c[1]), "+f"(c[2]), "+f"(c[3])
        : "r"(a[0]), "r"(a[1]), "r"(a[2]), "r"(a[3]), "r"(b[0]), "r"(b[1]));
}

// EPI==0: plain float2 stores. EPI==1: v += bias[col]; softplus; float2 stores.
template <int EPI>
__global__ __launch_bounds__(256, 2)
void hmma_gemm(const __nv_bfloat16* __restrict__ Ah, const __nv_bfloat16* __restrict__ Al,
               const __nv_bfloat16* __restrict__ Bh, const __nv_bfloat16* __restrict__ Bl,
               float* __restrict__ C, const float* __restrict__ bias,
               int K, int N, int Kpart)
{
    extern __shared__ __align__(128) char s[];
    const uint32_t sb = smem_u32(s);

    const int tid  = threadIdx.x;
    const int wid  = tid >> 5;
    const int lane = tid & 31;
    const int wm   = wid >> 2;
    const int wn   = wid & 3;

    const int brow  = blockIdx.y * 128;
    const int bcol  = blockIdx.x * 128;
    const int kbase = blockIdx.z * Kpart;
    C += (size_t)blockIdx.z * (size_t)(gridDim.y * 128) * N;

    float acc[4][4][4];
#pragma unroll
    for (int i = 0; i < 4; i++)
#pragma unroll
        for (int j = 0; j < 4; j++)
#pragma unroll
            for (int q = 0; q < 4; q++) acc[i][j][q] = 0.f;

    const int l_r0 = tid >> 2;
    const int l_k  = tid & 3;

#define LOAD_CHUNK(cidx, bufi)                                                    \
    {                                                                             \
        const int k0 = kbase + ((cidx) << 5);                                     \
        const uint32_t bbase = sb + (bufi) * BUF_BYTES;                           \
        _Pragma("unroll")                                                         \
        for (int i0 = 0; i0 < 2; i0++) {                                          \
            const int r = l_r0 + i0 * 64;                                         \
            const uint32_t so = (uint32_t)(r * 64 + ((l_k ^ ((r >> 1) & 3)) << 4)); \
            const size_t ga = (size_t)(brow + r) * K + k0 + l_k * 8;              \
            const size_t gb = (size_t)(bcol + r) * K + k0 + l_k * 8;              \
            CP_ASYNC16(bbase + so,        Ah + ga);                               \
            CP_ASYNC16(bbase + OAL + so,  Al + ga);                               \
            CP_ASYNC16(bbase + OBH + so,  Bh + gb);                               \
            CP_ASYNC16(bbase + OBL + so,  Bl + gb);                               \
        }                                                                         \
    }

    const int g  = lane >> 3;
    const int li = lane & 7;
    const int swz = (li >> 1) & 3;
    const int rowA = wm * 64 + li + (g & 1) * 8;
    const int khA  = g >> 1;
    const int rowB = wn * 32 + li + (g >> 1) * 8;
    const int khB  = g & 1;
    uint32_t aoffs[2], boffs[2];
#pragma unroll
    for (int sN = 0; sN < 2; sN++) {
        aoffs[sN] = (uint32_t)(rowA * 64 + (((2 * sN + khA) ^ swz) << 4));
        boffs[sN] = (uint32_t)(OBH + rowB * 64 + (((2 * sN + khB) ^ swz) << 4));
    }

#define COMPUTE_STEP(sidx, bofs)                                                  \
    {                                                                             \
        const uint32_t aA = sb + (bofs) + aoffs[sidx];                            \
        const uint32_t bB = sb + (bofs) + boffs[sidx];                            \
        uint32_t bh[4][2], bl[4][2];                                              \
        LDX4(bh[0][0], bh[0][1], bh[1][0], bh[1][1], bB);                         \
        LDX4(bh[2][0], bh[2][1], bh[3][0], bh[3][1], bB + 1024);                  \
        LDX4(bl[0][0], bl[0][1], bl[1][0], bl[1][1], bB + 8192);                  \
        LDX4(bl[2][0], bl[2][1], bl[3][0], bl[3][1], bB + 8192 + 1024);           \
        _Pragma("unroll")                                                         \
        for (int half = 0; half < 2; half++) {                                    \
            uint32_t ah[2][4], al[2][4];                                          \
            const uint32_t ab = aA + half * 2048;                                 \
            LDX4(ah[0][0], ah[0][1], ah[0][2], ah[0][3], ab);                     \
            LDX4(ah[1][0], ah[1][1], ah[1][2], ah[1][3], ab + 1024);              \
            LDX4(al[0][0], al[0][1], al[0][2], al[0][3], ab + OAL);               \
            LDX4(al[1][0], al[1][1], al[1][2], al[1][3], ab + OAL + 1024);        \
            _Pragma("unroll")                                                     \
            for (int m2 = 0; m2 < 2; m2++)                                        \
                _Pragma("unroll")                                                 \
                for (int nt = 0; nt < 4; nt++)                                    \
                    mma_bf16(acc[half * 2 + m2][nt], ah[m2], bh[nt]);             \
            _Pragma("unroll")                                                     \
            for (int m2 = 0; m2 < 2; m2++)                                        \
                _Pragma("unroll")                                                 \
                for (int nt = 0; nt < 4; nt++)                                    \
                    mma_bf16(acc[half * 2 + m2][nt], ah[m2], bl[nt]);             \
            _Pragma("unroll")                                                     \
            for (int m2 = 0; m2 < 2; m2++)                                        \
                _Pragma("unroll")                                                 \
                for (int nt = 0; nt < 4; nt++)                                    \
                    mma_bf16(acc[half * 2 + m2][nt], al[m2], bh[nt]);             \
        }                                                                         \
    }

    const int nchunks = Kpart >> 5;
    LOAD_CHUNK(0, 0); CP_COMMIT();
    if (nchunks > 1) { LOAD_CHUNK(1, 1); }
    CP_COMMIT();

    int buf = 0;
    for (int c = 0; c < nchunks; c++) {
        CP_WAIT1();
        __syncthreads();
        const int cn = c + 2;
        int nbuf = buf + 2; if (nbuf >= 3) nbuf -= 3;
        if (cn < nchunks) LOAD_CHUNK(cn, nbuf);
        CP_COMMIT();
        const uint32_t bofs = (uint32_t)(buf * BUF_BYTES);
        COMPUTE_STEP(0, bofs);
        COMPUTE_STEP(1, bofs);
        if (++buf == 3) buf = 0;
    }

    const int frow = lane >> 2;
    const int fcol = (lane & 3) << 1;
#pragma unroll
    for (int mt = 0; mt < 4; mt++) {
        const int row = brow + wm * 64 + mt * 16 + frow;
#pragma unroll
        for (int nt = 0; nt < 4; nt++) {
            const int col = bcol + wn * 32 + nt * 8 + fcol;
            float v0 = acc[mt][nt][0], v1 = acc[mt][nt][1];
            float v2 = acc[mt][nt][2], v3 = acc[mt][nt][3];
            if (EPI == 1) {
                const float b0 = bias[col], b1 = bias[col + 1];
                v0 += b0; v1 += b1; v2 += b0; v3 += b1;
                v0 = (v0 > 20.f) ? v0 : log1pf(__expf(v0));
                v1 = (v1 > 20.f) ? v1 : log1pf(__expf(v1));
                v2 = (v2 > 20.f) ? v2 : log1pf(__expf(v2));
                v3 = (v3 > 20.f) ? v3 : log1pf(__expf(v3));
            }
            *(float2*)&C[(size_t)row * N + col]       = make_float2(v0, v1);
            *(float2*)&C[(size_t)(row + 8) * N + col] = make_float2(v2, v3);
        }
    }
#undef LOAD_CHUNK
#undef COMPUTE_STEP
}

// ---------- split-K=2 reduce (GEMM4) ----------------------------------------
__global__ __launch_bounds__(256)
void reduce2_kernel(const float* __restrict__ p, float* __restrict__ out, int n4)
{
    int i = blockIdx.x * 256 + threadIdx.x;
    if (i >= n4) return;
    const float4* p0 = (const float4*)p;
    const float4* p1 = p0 + n4;
    float4 a = p0[i], b = p1[i];
    ((float4*)out)[i] = make_float4(a.x + b.x, a.y + b.y, a.z + b.z, a.w + b.w);
}

// ---------- split-K=16 reduce for xdbl (+ fold delta_r bf16 split) -----------
__global__ __launch_bounds__(256)
void reduce16_xdbl_kernel()
{
    const int n4 = NROWS * XDBL_P / 4;      // 65536
    int i = blockIdx.x * 256 + threadIdx.x;
    if (i >= n4) return;
    float4 s = make_float4(0.f, 0.f, 0.f, 0.f);
    const float4* p = (const float4*)g_part;
#pragma unroll
    for (int k = 0; k < 16; k++) {
        float4 v = p[(size_t)k * n4 + i];
        s.x += v.x; s.y += v.y; s.z += v.z; s.w += v.w;
    }
    ((float4*)g_xdbl)[i] = s;
    const int row = i >> 5;
    const int c4  = (i & 31) << 2;
    if (c4 < DT_RANK) {
        const size_t o = (size_t)row * DT_RANK + c4;
        float vv[4] = {s.x, s.y, s.z, s.w};
#pragma unroll
        for (int q = 0; q < 4; q++) {
            __nv_bfloat16 h = __float2bfloat16(vv[q]);
            g_drh[o + q] = h;
            g_drl[o + q] = __float2bfloat16(vv[q] - __bfloat162float(h));
        }
    }
}

// ---- fused prep: x split (vec4) + transpose+split of weights + W_x pad -----
__device__ __forceinline__ void tsplit_tile(
    const float* __restrict__ W, __nv_bfloat16* __restrict__ Th,
    __nv_bfloat16* __restrict__ Tl, int K, int N, int bx, int by, int tid)
{
    __shared__ float t[32][33];
    const int tx = tid & 31;
    const int ty = tid >> 5;
    const int n0 = bx * 32;
    const int k0 = by * 32;
#pragma unroll
    for (int s2 = 0; s2 < 32; s2 += 8)
        t[ty + s2][tx] = W[(size_t)(k0 + ty + s2) * N + n0 + tx];
    __syncthreads();
#pragma unroll
    for (int s2 = 0; s2 < 32; s2 += 8) {
        float v = t[tx][ty + s2];
        __nv_bfloat16 h = __float2bfloat16(v);
        const size_t o = (size_t)(n0 + ty + s2) * K + k0 + tx;
        Th[o] = h;
        Tl[o] = __float2bfloat16(v - __bfloat162float(h));
    }
}

// [0,2048): x split vec4 | [2048,6144): W_in | [6144,8192): W_out
// [8192,8320): W_dt | [8320,8512): W_x tiles | [8512,8768): W_x pad zero
__global__ __launch_bounds__(256)
void prep_all_kernel(const float* __restrict__ x, const float* __restrict__ W_in,
                     const float* __restrict__ W_out, const float* __restrict__ W_dt,
                     const float* __restrict__ W_x)
{
    const int id = blockIdx.x;
    const int tid = threadIdx.x;
    if (id < 2048) {
        const int i4 = (id * 256 + tid) * 4;
        float4 v = *(const float4*)(x + i4);
        float vv[4] = {v.x, v.y, v.z, v.w};
#pragma unroll
        for (int q = 0; q < 4; q++) {
            __nv_bfloat16 h = __float2bfloat16(vv[q]);
            g_xh[i4 + q] = h;
            g_xl[i4 + q] = __float2bfloat16(vv[q] - __bfloat162float(h));
        }
    } else if (id < 6144) {
        const int j = id - 2048;
        tsplit_tile(W_in, g_winh, g_winl, D_MODEL, 2 * D_INNER, j & 127, j >> 7, tid);
    } else if (id < 8192) {
        const int j = id - 6144;
        tsplit_tile(W_out, g_woh, g_wol, D_INNER, D_MODEL, j & 31, j >> 5, tid);
    } else if (id < 8320) {
        const int j = id - 8192;
        tsplit_tile(W_dt, g_wdth, g_wdtl, DT_RANK, D_INNER, j & 63, j >> 6, tid);
    } else if (id < 8512) {
        const int j = id - 8320;
        tsplit_tile(W_x, g_wxh, g_wxl, D_INNER, XDBL_N, j % 3, j / 3, tid);
    } else {
        const int j = (id - 8512) * 256 + tid;
        const int base = XDBL_N * D_INNER;
        g_wxh[base + j] = __float2bfloat16(0.f);
        g_wxl[base + j] = __float2bfloat16(0.f);
    }
}

// ---------- depthwise causal conv (k=4) + SiLU, 8 steps/thread --------------
__global__ __launch_bounds__(256)
void conv_silu8_kernel(const float* __restrict__ conv_w, const float* __restrict__ conv_b)
{
    int i = blockIdx.x * 256 + threadIdx.x;
    if (i >= (NROWS / 8) * D_INNER) return;
    const int d    = i & (D_INNER - 1);
    const int grp  = i >> 11;
    const int row0 = grp << 3;
    const int l0   = row0 & (SEQ - 1);

    const float w0 = conv_w[d * 4 + 0];
    const float w1 = conv_w[d * 4 + 1];
    const float w2 = conv_w[d * 4 + 2];
    const float w3 = conv_w[d * 4 + 3];
    const float bb = conv_b[d];

    const float* xe = g_xz + (size_t)row0 * (2 * D_INNER) + d;
    float xv[11];
    if (l0 > 0) {
        xv[0] = xe[-3 * 2 * D_INNER];
        xv[1] = xe[-2 * 2 * D_INNER];
        xv[2] = xe[-1 * 2 * D_INNER];
    } else {
        xv[0] = xv[1] = xv[2] = 0.f;
    }
#pragma unroll
    for (int k = 0; k < 8; k++)
        xv[3 + k] = xe[(size_t)k * 2 * D_INNER];

    const float* zp = xe + D_INNER;
#pragma unroll
    for (int k = 0; k < 8; k++) {
        float a = bb;
        a = fmaf(w0, xv[k],     a);
        a = fmaf(w1, xv[k + 1], a);
        a = fmaf(w2, xv[k + 2], a);
        a = fmaf(w3, xv[k + 3], a);
        const float xc = a / (1.f + __expf(-a));
        const float zv = zp[(size_t)k * 2 * D_INNER];
        const float zs = zv / (1.f + __expf(-zv));
        const size_t o = (size_t)(row0 + k) * D_INNER + d;
        g_xc[o] = xc;
        g_zs[o] = zs;
        __nv_bfloat16 h = __float2bfloat16(xc);
        g_xch[o] = h;
        g_xcl[o] = __float2bfloat16(xc - __bfloat162float(h));
    }
}

// ================== fused chunked selective scan (r12 layout) ================
__global__ __launch_bounds__(256)
void scan_fused(const float* __restrict__ A_log, const float* __restrict__ Dp)
{
    __shared__ float sm_hend[NCH][32];
    __shared__ float sm_P[NCH][32];
    __shared__ float sm_hin[NCH][32];

    const int tid    = threadIdx.x;
    const int w      = tid >> 5;
    const int lane   = tid & 31;
    const int half   = lane >> 4;
    const int lane16 = lane & 15;
    const int chan   = (blockIdx.x << 1) | half;
    const int b      = blockIdx.y;

    const float Aval = -__expf(A_log[chan * D_STATE + lane16]);
    const float Dd   = Dp[chan];

    const size_t rbase = (size_t)b * SEQ + (size_t)w * CHUNK;

    // ---- phase 1
    {
        const float* dl = g_delta + rbase * D_INNER + chan;
        const float* xp = g_xc    + rbase * D_INNER + chan;
        const float* bp = g_xdbl  + rbase * XDBL_P + DT_RANK + lane16;

        float pdv[4], pxv[4], pBn[4];
#pragma unroll
        for (int u = 0; u < 4; u++) {
            pdv[u] = dl[u * D_INNER];
            pxv[u] = xp[u * D_INNER];
            pBn[u] = bp[u * XDBL_P];
        }
        float h = 0.f, P = 1.f;
        for (int l = 0; l < CHUNK; l += 4) {
            float dv[4], xv[4], Bn[4], dA[4];
#pragma unroll
            for (int u = 0; u < 4; u++) { dv[u] = pdv[u]; xv[u] = pxv[u]; Bn[u] = pBn[u]; }
            dl += 4 * D_INNER; xp += 4 * D_INNER; bp += 4 * XDBL_P;
            if (l + 4 < CHUNK) {
#pragma unroll
                for (int u = 0; u < 4; u++) {
                    pdv[u] = dl[u * D_INNER];
                    pxv[u] = xp[u * D_INNER];
                    pBn[u] = bp[u * XDBL_P];
                }
            }
#pragma unroll
            for (int u = 0; u < 4; u++) dA[u] = __expf(dv[u] * Aval);
#pragma unroll
            for (int u = 0; u < 4; u++) {
                h = fmaf(dA[u], h, dv[u] * xv[u] * Bn[u]);
                P *= dA[u];
            }
        }
        sm_hend[w][lane] = h;
        sm_P[w][lane]    = P;
    }
    __syncthreads();

    if (tid < 32) {
        float H = 0.f;
#pragma unroll
        for (int c = 0; c < NCH; c++) {
            sm_hin[c][tid] = H;
            H = fmaf(sm_P[c][tid], H, sm_hend[c][tid]);
        }
    }
    __syncthreads();

    // ---- phase 3
    {
        const float* dl = g_delta + rbase * D_INNER + chan;
        const float* xp = g_xc    + rbase * D_INNER + chan;
        const float* zp = g_zs    + rbase * D_INNER + chan;
        __nv_bfloat16* yh = g_yh  + rbase * D_INNER + chan;
        __nv_bfloat16* yl = g_yl  + rbase * D_INNER + chan;
        const float* bp = g_xdbl  + rbase * XDBL_P + DT_RANK + lane16;
        const float* cp = bp + D_STATE;

        float h = sm_hin[w][lane];

        float pdv[4], pxv[4], pzv[4], pBn[4], pCn[4];
#pragma unroll
        for (int u = 0; u < 4; u++) {
            pdv[u] = dl[u * D_INNER];
            pxv[u] = xp[u * D_INNER];
            pzv[u] = zp[u * D_INNER];
            pBn[u] = bp[u * XDBL_P];
            pCn[u] = cp[u * XDBL_P];
        }

        for (int l = 0; l < CHUNK; l += 4) {
            float dv[4], xv[4], Bn[4], Cn[4], zv[4], dA[4];
#pragma unroll
            for (int u = 0; u < 4; u++) {
                dv[u] = pdv[u]; xv[u] = pxv[u]; zv[u] = pzv[u];
                Bn[u] = pBn[u]; Cn[u] = pCn[u];
            }
            dl += 4 * D_INNER; xp += 4 * D_INNER; zp += 4 * D_INNER;
            bp += 4 * XDBL_P;  cp += 4 * XDBL_P;
            if (l + 4 < CHUNK) {
#pragma unroll
                for (int u = 0; u < 4; u++) {
                    pdv[u] = dl[u * D_INNER];
                    pxv[u] = xp[u * D_INNER];
                    pzv[u] = zp[u * D_INNER];
                    pBn[u] = bp[u * XDBL_P];
                    pCn[u] = cp[u * XDBL_P];
                }
            }

#pragma unroll
            for (int u = 0; u < 4; u++) dA[u] = __expf(dv[u] * Aval);

            float contrib[4];
#pragma unroll
            for (int u = 0; u < 4; u++) {
                h = fmaf(dA[u], h, dv[u] * xv[u] * Bn[u]);
                contrib[u] = h * Cn[u];
            }
#pragma unroll
            for (int u = 0; u < 4; u++) {
                contrib[u] += __shfl_down_sync(0xffffffffu, contrib[u], 8, 16);
                contrib[u] += __shfl_down_sync(0xffffffffu, contrib[u], 4, 16);
                contrib[u] += __shfl_down_sync(0xffffffffu, contrib[u], 2, 16);
                contrib[u] += __shfl_down_sync(0xffffffffu, contrib[u], 1, 16);
            }
            if (lane16 == 0) {
#pragma unroll
                for (int u = 0; u < 4; u++) {
                    float v = fmaf(xv[u], Dd, contrib[u]) * zv[u];
                    __nv_bfloat16 hh = __float2bfloat16(v);
                    yh[(size_t)(l + u) * D_INNER] = hh;
                    yl[(size_t)(l + u) * D_INNER] =
                        __float2bfloat16(v - __bfloat162float(hh));
                }
            }
        }
    }
}

// ---------------- launch ----------------------------------------------------
extern "C" void kernel_launch(void* const* d_in, const int* in_sizes, int n_in,
                              void* d_out, int out_size)
{
    const float* x      = (const float*)d_in[0];
    const float* W_in   = (const float*)d_in[1];
    const float* conv_w = (const float*)d_in[2];
    const float* conv_b = (const float*)d_in[3];
    const float* W_x    = (const float*)d_in[4];
    const float* W_dt   = (const float*)d_in[5];
    const float* b_dt   = (const float*)d_in[6];
    const float* A_log  = (const float*)d_in[7];
    const float* Dp     = (const float*)d_in[8];
    const float* W_out  = (const float*)d_in[9];
    float* out = (float*)d_out;

    float *xz, *part, *delta;
    __nv_bfloat16 *xh, *xl, *xch, *xcl, *winh, *winl, *wxh, *wxl;
    __nv_bfloat16 *yh, *yl, *woh, *wol, *drh, *drl, *wdth, *wdtl;
    cudaGetSymbolAddress((void**)&xz,    g_xz);
    cudaGetSymbolAddress((void**)&part,  g_part);
    cudaGetSymbolAddress((void**)&delta, g_delta);
    cudaGetSymbolAddress((void**)&xh,   g_xh);
    cudaGetSymbolAddress((void**)&xl,   g_xl);
    cudaGetSymbolAddress((void**)&xch,  g_xch);
    cudaGetSymbolAddress((void**)&xcl,  g_xcl);
    cudaGetSymbolAddress((void**)&winh, g_winh);
    cudaGetSymbolAddress((void**)&winl, g_winl);
    cudaGetSymbolAddress((void**)&wxh,  g_wxh);
    cudaGetSymbolAddress((void**)&wxl,  g_wxl);
    cudaGetSymbolAddress((void**)&yh,   g_yh);
    cudaGetSymbolAddress((void**)&yl,   g_yl);
    cudaGetSymbolAddress((void**)&woh,  g_woh);
    cudaGetSymbolAddress((void**)&wol,  g_wol);
    cudaGetSymbolAddress((void**)&drh,  g_drh);
    cudaGetSymbolAddress((void**)&drl,  g_drl);
    cudaGetSymbolAddress((void**)&wdth, g_wdth);
    cudaGetSymbolAddress((void**)&wdtl, g_wdtl);

    const int HSMEM = 3 * BUF_BYTES;  // 98304
    cudaFuncSetAttribute(hmma_gemm<0>, cudaFuncAttributeMaxDynamicSharedMemorySize, HSMEM);
    cudaFuncSetAttribute(hmma_gemm<1>, cudaFuncAttributeMaxDynamicSharedMemorySize, HSMEM);

    // 0) fused prep
    prep_all_kernel<<<8768, 256>>>(x, W_in, W_out, W_dt, W_x);

    // 1) xz = x @ W_in
    hmma_gemm<0><<<dim3(2 * D_INNER / 128, NROWS / 128, 1), 256, HSMEM>>>(
        xh, xl, winh, winl, xz, nullptr, D_MODEL, 2 * D_INNER, D_MODEL);

    // 2) xc = silu(conv(x_e)+b), zs = silu(z), xc bf16 split
    conv_silu8_kernel<<<(NROWS / 8 * D_INNER + 255) / 256, 256>>>(conv_w, conv_b);

    // 3) xdbl = xc @ W_x  (HMMA, N=128 padded, split-K=16)
    hmma_gemm<0><<<dim3(1, NROWS / 128, 16), 256, HSMEM>>>(
        xch, xcl, wxh, wxl, part, nullptr, D_INNER, XDBL_P, D_INNER / 16);
    reduce16_xdbl_kernel<<<(NROWS * XDBL_P / 4 + 255) / 256, 256>>>();

    // 4) delta = softplus(delta_r @ W_dt + b_dt)  (HMMA, K=64)
    hmma_gemm<1><<<dim3(D_INNER / 128, NROWS / 128, 1), 256, HSMEM>>>(
        drh, drl, wdth, wdtl, delta, b_dt, DT_RANK, D_INNER, DT_RANK);

    // 5) fused chunked selective scan -> yh/yl
    scan_fused<<<dim3(D_INNER / 2, B_SZ), 256>>>(A_log, Dp);

    // 6) out = y @ W_out  (split-K=2)
    hmma_gemm<0><<<dim3(D_MODEL / 128, NROWS / 128, 2), 256, HSMEM>>>(
        yh, yl, woh, wol, part, nullptr, D_INNER, D_MODEL, D_INNER / 2);
    reduce2_kernel<<<(NROWS * D_MODEL / 4 + 255) / 256, 256>>>(
        part, out, NROWS * D_MODEL / 4);
}